// round 2
// baseline (speedup 1.0000x reference)
#include <cuda_runtime.h>

// y[o*16+k, n_out, m] = sum_{i<64, j<3} patches[o*64+i, n_src, j, m] * W[i, k, j]
// patches[c, n, j, m] = x[c, n, (m+j-2) mod 56] if 1 <= m+j <= 56 else 0
// n_out = (n_src + 1) mod 56   (output H roll folded in)
//
// smem xs[i][u], u in [0,58): xs[i][0]=xs[i][57]=0, xs[i][1+((w+1)%56)] = x[c,n_src,w]
// so patches[c, n_src, j, m] == xs[i][m + j].

__global__ __launch_bounds__(128)
void shiftconv_kernel(const float* __restrict__ x,
                      const float* __restrict__ Wg,
                      float* __restrict__ y)
{
    __shared__ float xs[64 * 58];     // 14848 B
    __shared__ float Ws[64 * 48];     // 12288 B, layout [i][k][j] same as global

    const int n_src = blockIdx.x;     // 0..55
    const int o     = blockIdx.y;     // 0..1
    const int tid   = threadIdx.x;    // 0..127

    // ---- stage W (shared by both groups) ----
    #pragma unroll
    for (int idx = tid; idx < 64 * 48; idx += 128)
        Ws[idx] = Wg[idx];

    // ---- stage x row-slab with W-dim circular shift + pad folded in ----
    const float* xbase = x + (o * 64) * 3136 + n_src * 56;
    #pragma unroll
    for (int idx = tid; idx < 64 * 56; idx += 128) {
        const int i = idx / 56;
        const int w = idx - i * 56;
        const float v = xbase[i * 3136 + w];
        int u = w + 2;                // 1 + ((w + 1) % 56)
        if (u > 56) u -= 56;
        xs[i * 58 + u] = v;
    }
    if (tid < 64) {
        xs[tid * 58 + 0]  = 0.0f;
        xs[tid * 58 + 57] = 0.0f;
    }
    __syncthreads();

    // ---- compute: thread (k, g) -> output k, m in [g*7, g*7+7) ----
    const int k  = tid & 15;
    const int g  = tid >> 4;
    const int m0 = g * 7;

    float acc[7];
    #pragma unroll
    for (int t = 0; t < 7; t++) acc[t] = 0.0f;

    #pragma unroll 4
    for (int i = 0; i < 64; i++) {
        const float* wrow = &Ws[i * 48 + k * 3];
        const float w0 = wrow[0];
        const float w1 = wrow[1];
        const float w2 = wrow[2];

        const float* xrow = &xs[i * 58 + m0];
        float xv[9];
        #pragma unroll
        for (int u = 0; u < 9; u++) xv[u] = xrow[u];

        #pragma unroll
        for (int t = 0; t < 7; t++)
            acc[t] = fmaf(w2, xv[t + 2],
                     fmaf(w1, xv[t + 1],
                     fmaf(w0, xv[t], acc[t])));
    }

    // ---- write with H-dim circular shift folded in ----
    int n_out = n_src + 1;
    if (n_out == 56) n_out = 0;
    float* ybase = y + (o * 16 + k) * 3136 + n_out * 56 + m0;
    #pragma unroll
    for (int t = 0; t < 7; t++) ybase[t] = acc[t];
}

extern "C" void kernel_launch(void* const* d_in, const int* in_sizes, int n_in,
                              void* d_out, int out_size)
{
    const float* x  = (const float*)d_in[0];   // (1,128,56,56) = 401408
    const float* Wg = (const float*)d_in[1];   // (64,16,3)     = 3072
    float* y = (float*)d_out;                  // (1,32,56,56)  = 100352

    dim3 grid(56, 2);
    shiftconv_kernel<<<grid, 128>>>(x, Wg, y);
}

// round 4
// speedup vs baseline: 1.0584x; 1.0584x over previous
#include <cuda_runtime.h>

// y[o*16+k, n_out, m] = sum_{i<64, j<3} xs[i][m+j] * W[i, k, j]
// xs is the W-rolled, padded input row slab; n_out = (n_src+1) % 56.
//
// 512 threads: slice = tid>>7 handles i in [slice*16, slice*16+16).
// Thread-in-slice (k = t&15, g = t>>4) computes outputs (k, m = g*7 .. g*7+6).
// Slices 1..3 spill partial acc to smem (stride 9, conflict-free); slice 0
// accumulates and writes.

__global__ __launch_bounds__(512)
void shiftconv_kernel(const float* __restrict__ x,
                      const float* __restrict__ Wg,
                      float* __restrict__ y)
{
    __shared__ float xs[64 * 58];      // 14848 B
    __shared__ float Ws[64 * 48];      // 12288 B, layout [i][k][j]
    __shared__ float ps[3 * 128 * 9];  // 13824 B, partial sums, stride 9

    const int n_src = blockIdx.x;      // 0..55
    const int o     = blockIdx.y;      // 0..1
    const int tid   = threadIdx.x;     // 0..511

    // ---- stage W (shared by both groups) ----
    #pragma unroll
    for (int idx = tid; idx < 64 * 48; idx += 512)
        Ws[idx] = Wg[idx];

    // ---- stage x row-slab, W-dim circular shift + zero pad folded in ----
    const float* xbase = x + (o * 64) * 3136 + n_src * 56;
    #pragma unroll
    for (int idx = tid; idx < 64 * 56; idx += 512) {
        const int i = idx / 56;
        const int w = idx - i * 56;
        const float v = xbase[i * 3136 + w];
        int u = w + 2;                 // 1 + ((w + 1) % 56)
        if (u > 56) u -= 56;
        xs[i * 58 + u] = v;
    }
    if (tid < 64) {
        xs[tid * 58 + 0]  = 0.0f;
        xs[tid * 58 + 57] = 0.0f;
    }
    __syncthreads();

    const int slice = tid >> 7;        // 0..3 -> i-range
    const int t128  = tid & 127;
    const int k     = t128 & 15;
    const int g     = t128 >> 4;
    const int m0    = g * 7;
    const int i0    = slice * 16;

    float acc[7];
    #pragma unroll
    for (int t = 0; t < 7; t++) acc[t] = 0.0f;

    #pragma unroll 4
    for (int ii = 0; ii < 16; ii++) {
        const int i = i0 + ii;
        const float* wrow = &Ws[i * 48 + k * 3];
        const float w0 = wrow[0];
        const float w1 = wrow[1];
        const float w2 = wrow[2];

        const float* xrow = &xs[i * 58 + m0];
        float xv[9];
        #pragma unroll
        for (int u = 0; u < 9; u++) xv[u] = xrow[u];

        #pragma unroll
        for (int t = 0; t < 7; t++)
            acc[t] = fmaf(w2, xv[t + 2],
                     fmaf(w1, xv[t + 1],
                     fmaf(w0, xv[t], acc[t])));
    }

    // ---- cross-slice reduction ----
    if (slice > 0) {
        float* p = &ps[(slice - 1) * 1152 + t128 * 9];
        #pragma unroll
        for (int t = 0; t < 7; t++) p[t] = acc[t];
    }
    __syncthreads();

    if (slice == 0) {
        #pragma unroll
        for (int s = 0; s < 3; s++) {
            const float* p = &ps[s * 1152 + t128 * 9];
            #pragma unroll
            for (int t = 0; t < 7; t++) acc[t] += p[t];
        }

        int n_out = n_src + 1;
        if (n_out == 56) n_out = 0;
        float* ybase = y + (o * 16 + k) * 3136 + n_out * 56 + m0;
        #pragma unroll
        for (int t = 0; t < 7; t++) ybase[t] = acc[t];
    }
}

extern "C" void kernel_launch(void* const* d_in, const int* in_sizes, int n_in,
                              void* d_out, int out_size)
{
    const float* x  = (const float*)d_in[0];   // (1,128,56,56) = 401408
    const float* Wg = (const float*)d_in[1];   // (64,16,3)     = 3072
    float* y = (float*)d_out;                  // (1,32,56,56)  = 100352

    dim3 grid(56, 2);
    shiftconv_kernel<<<grid, 512>>>(x, Wg, y);
}